// round 14
// baseline (speedup 1.0000x reference)
#include <cuda_runtime.h>

#define H 32
#define WPB 7            // warps per block; each warp = 2 batch rows
#define THREADS (WPB*32)
#define CHUNK 32         // deferred-output chunk (dynamic smem)
#define RSTRIDE 48       // ring: row B offset (floats) -> 16-bank shift
#define TSTR2R 1072      // hT: row B offset within warp (1072%32==16)
#define HT_WSTR 2144     // hT: per-warp stride (2144%32==0, pattern preserved)

// dynamic smem layout (floats):
//   [0, 1344)        ring  [WPB][2][2*RSTRIDE]
//   [1344, 1377)     wout  [H+1] ([32]=b_out)
//   [1392, 16400)    hT    per warp HT_WSTR, per row TSTR2R, unit stride 33
#define RING_OFF 0
#define WOUT_OFF 1344
#define HT_OFF   1392
#define SMEM_FLOATS 16400
#define SMEM_BYTES (SMEM_FLOATS * 4)

typedef unsigned long long ull;

// zero-instruction ordering fence (same-warp MIO is in-order; R9/R12 verified)
#define CFENCE() asm volatile("" ::: "memory")

// ---------- packed f32x2 helpers (sm_103a dual FP32 pipe) ----------
__device__ __forceinline__ ull ffma2(ull a, ull b, ull c) {
    ull d;
    asm("fma.rn.f32x2 %0, %1, %2, %3;" : "=l"(d) : "l"(a), "l"(b), "l"(c));
    return d;
}
__device__ __forceinline__ ull subf2(ull a, ull b) {
    ull d;
    asm("sub.rn.f32x2 %0, %1, %2;" : "=l"(d) : "l"(a), "l"(b));
    return d;
}
__device__ __forceinline__ ull mulf2(ull a, ull b) {
    ull d;
    asm("mul.rn.f32x2 %0, %1, %2;" : "=l"(d) : "l"(a), "l"(b));
    return d;
}
__device__ __forceinline__ float tanh_ap(float x) {
    float r; asm("tanh.approx.f32 %0, %1;" : "=f"(r) : "f"(x)); return r;
}
__device__ __forceinline__ ull pack2(float lo, float hi) {
    ull d;
    asm("mov.b64 %0, {%1, %2};" : "=l"(d) : "f"(lo), "f"(hi));
    return d;
}
__device__ __forceinline__ void unpack2(ull a, float& lo, float& hi) {
    asm("mov.b64 {%0, %1}, %2;" : "=f"(lo), "=f"(hi) : "l"(a));
}
// (a.lo + a.hi, b.lo + b.hi): horizontal sums of two packed accumulators,
// repacked as one f32x2 lane pair. Movs are register-pair aliasing (mostly
// free); the add runs on the fma pipe as ONE packed op instead of two FADDs.
__device__ __forceinline__ ull zip_add(ull a, ull b) {
    float alo, ahi, blo, bhi;
    unpack2(a, alo, ahi);
    unpack2(b, blo, bhi);
    ull lo = pack2(alo, blo), hi = pack2(ahi, bhi);
    ull r;
    asm("add.rn.f32x2 %0, %1, %2;" : "=l"(r) : "l"(lo), "l"(hi));
    return r;
}
__device__ __forceinline__ ull tanh2(ull a) {
    float lo, hi; unpack2(a, lo, hi);
    return pack2(tanh_ap(lo), tanh_ap(hi));
}

// One warp = 2 batch rows (half-warp per row); lane owns hidden units u0, u0+16
// of its row. Dot products scalar-per-unit (R12 structure, unchanged); the
// gate epilogue is fully f32x2-packed across the lane's two units.
// grid=147 x 7 warps covers 1024 row-pairs, single wave, all SMs.
__global__ void __launch_bounds__(THREADS, 1)
gru_warp_kernel(const float* __restrict__ x,     // [B,T]
                const float* __restrict__ h0,    // [B,H]
                const float* __restrict__ W_ih,  // [3H] (I=1)
                const float* __restrict__ W_hh,  // [3H,H]
                const float* __restrict__ b_ih,  // [3H]
                const float* __restrict__ b_hh,  // [3H]
                const float* __restrict__ W_out, // [H]
                const float* __restrict__ b_out, // [1]
                float* __restrict__ y,           // [B,T]
                float* __restrict__ hn,          // [B,H]
                int B, int T)
{
    extern __shared__ __align__(16) float smem[];
    float* ring   = smem + RING_OFF;
    float* wout_s = smem + WOUT_OFF;
    float* hTall  = smem + HT_OFF;

    const int lane = threadIdx.x & 31;
    const int w    = threadIdx.x >> 5;
    const int npairs = B >> 1;
    const int p    = blockIdx.x * WPB + w;

    if (threadIdx.x < H) wout_s[threadIdx.x] = W_out[threadIdx.x];
    if (threadIdx.x == H) wout_s[H] = b_out[0];
    __syncthreads();
    if (p >= npairs) return;

    const int u0  = lane & 15;     // first hidden unit this lane owns
    const int r   = lane >> 4;     // which row of the pair this half-warp runs
    const int row = 2 * p + r;     // global batch row

    // ---- recurrent weights for units u0 and u0+16 (6 gate rows), packed pairs.
    //      r/z rows pre-scaled by 0.5: sigmoid(a) = 0.5 + 0.5*tanh(a/2). ----
    ull Wr0[16], Wz0[16], Wn0[16], Wr1[16], Wz1[16], Wn1[16];
    {
        const ull HALF2 = 0x3F0000003F000000ull;  // (0.5f, 0.5f)
        const int u1 = u0 + 16;
        const ull* wr0 = (const ull*)(W_hh + (size_t)u0 * H);
        const ull* wz0 = (const ull*)(W_hh + (size_t)(H + u0) * H);
        const ull* wn0 = (const ull*)(W_hh + (size_t)(2 * H + u0) * H);
        const ull* wr1 = (const ull*)(W_hh + (size_t)u1 * H);
        const ull* wz1 = (const ull*)(W_hh + (size_t)(H + u1) * H);
        const ull* wn1 = (const ull*)(W_hh + (size_t)(2 * H + u1) * H);
        #pragma unroll
        for (int k = 0; k < 16; k++) {
            Wr0[k] = mulf2(wr0[k], HALF2);
            Wz0[k] = mulf2(wz0[k], HALF2);
            Wn0[k] = wn0[k];
            Wr1[k] = mulf2(wr1[k], HALF2);
            Wz1[k] = mulf2(wz1[k], HALF2);
            Wn1[k] = wn1[k];
        }
    }
    const int u1 = u0 + 16;
    // packed per-lane constants (unit u0 in lo, unit u1 in hi)
    const ull wihr2 = pack2(0.5f * W_ih[u0],     0.5f * W_ih[u1]);
    const ull wihz2 = pack2(0.5f * W_ih[H + u0], 0.5f * W_ih[H + u1]);
    const ull wihn2 = pack2(W_ih[2 * H + u0],    W_ih[2 * H + u1]);
    const ull bin2  = pack2(b_ih[2 * H + u0],    b_ih[2 * H + u1]);
    // gate biases folded into accumulator inits (lo half of packed pair)
    const ull ir0 = pack2(0.5f * (b_ih[u0] + b_hh[u0]), 0.0f);
    const ull ir1 = pack2(0.5f * (b_ih[u1] + b_hh[u1]), 0.0f);
    const ull iz0 = pack2(0.5f * (b_ih[H + u0] + b_hh[H + u0]), 0.0f);
    const ull iz1 = pack2(0.5f * (b_ih[H + u1] + b_hh[H + u1]), 0.0f);
    const ull in0 = pack2(b_hh[2 * H + u0], 0.0f);   // n hidden bias (inside r*)
    const ull in1 = pack2(b_hh[2 * H + u1], 0.0f);
    const ull HALF2 = 0x3F0000003F000000ull;

    float* ringw = ring + w * (2 * 2 * RSTRIDE);     // [2][96]
    float* hTrow = hTall + w * HT_WSTR + r * TSTR2R; // this row's 32x33 history

    ull h2 = pack2(h0[(size_t)row * H + u0], h0[(size_t)row * H + u1]);
    {
        float hA, hB; unpack2(h2, hA, hB);
        ringw[96 + r * RSTRIDE + u0] = hA;   // step 0 reads parity 1
        ringw[96 + r * RSTRIDE + u1] = hB;
    }
    __syncwarp();

    const float* xrow = x + (size_t)row * T;
    float*       yrow = y + (size_t)row * T;

    float xv0 = xrow[u0];                  // first chunk x, steps 0..15
    float xv1 = xrow[16 + u0];             // first chunk x, steps 16..31

    for (int t0 = 0; t0 < T; t0 += CHUNK) {
        #pragma unroll 2
        for (int s = 0; s < CHUNK; s++) {
            const int rd = (s & 1) ^ 1;
            const int wb = (s & 1);

            const float xsrc = (s & 16) ? xv1 : xv0;
            const float xt = __shfl_sync(0xffffffffu, xsrc, s & 15, 16);
            const ull xt2 = pack2(xt, xt);

            const ulonglong2* hp = (const ulonglong2*)&ringw[rd * 96 + r * RSTRIDE];
            ull ar0 = ir0, az0 = iz0, an0 = in0;
            ull ar1 = ir1, az1 = iz1, an1 = in1;
            #pragma unroll
            for (int q = 0; q < 8; q++) {
                const ulonglong2 hv = hp[q];     // 4 h values of this row
                ar0 = ffma2(hv.x, Wr0[2 * q],     ar0);
                az0 = ffma2(hv.x, Wz0[2 * q],     az0);
                an0 = ffma2(hv.x, Wn0[2 * q],     an0);
                ar1 = ffma2(hv.x, Wr1[2 * q],     ar1);
                az1 = ffma2(hv.x, Wz1[2 * q],     az1);
                an1 = ffma2(hv.x, Wn1[2 * q],     an1);
                ar0 = ffma2(hv.y, Wr0[2 * q + 1], ar0);
                az0 = ffma2(hv.y, Wz0[2 * q + 1], az0);
                an0 = ffma2(hv.y, Wn0[2 * q + 1], an0);
                ar1 = ffma2(hv.y, Wr1[2 * q + 1], ar1);
                az1 = ffma2(hv.y, Wz1[2 * q + 1], az1);
                an1 = ffma2(hv.y, Wn1[2 * q + 1], an1);
            }
            // fully packed epilogue: (unit u0, unit u1) as one f32x2 stream
            const ull gr2 = zip_add(ar0, ar1);   // (gr_u0, gr_u1)
            const ull gz2 = zip_add(az0, az1);
            const ull gn2 = zip_add(an0, an1);
            const ull rg2 = ffma2(HALF2, tanh2(ffma2(xt2, wihr2, gr2)), HALF2);
            const ull zg2 = ffma2(HALF2, tanh2(ffma2(xt2, wihz2, gz2)), HALF2);
            const ull ng2 = tanh2(ffma2(rg2, gn2, ffma2(xt2, wihn2, bin2)));
            h2 = ffma2(zg2, subf2(h2, ng2), ng2);   // (1-z)*n + z*h

            float hA, hB; unpack2(h2, hA, hB);
            ringw[wb * 96 + r * RSTRIDE + u0] = hA;
            ringw[wb * 96 + r * RSTRIDE + u1] = hB;
            hTrow[33 * u0 + s] = hA;          // conflict-free (derived bank map)
            hTrow[33 * u1 + s] = hB;
            CFENCE();         // same-warp in-order MIO: no WARPSYNC needed
        }

        // Prefetch next chunk's x while the y-phase runs.
        float xn0 = 0.0f, xn1 = 0.0f;
        if (t0 + CHUNK < T) {
            xn0 = xrow[t0 + CHUNK + u0];
            xn1 = xrow[t0 + CHUNK + 16 + u0];
        }

        // Deferred y: each lane produces 2 outputs (row r, steps u0 and u0+16),
        // 4 independent 16-deep FMA chains to cut exposed latency.
        float a0 = wout_s[H], a1 = wout_s[H];   // b_out folded into init
        float b0 = 0.0f,      b1 = 0.0f;
        #pragma unroll
        for (int j = 0; j < 16; j++) {
            a0 = fmaf(hTrow[33 * j + u0],             wout_s[j],      a0);
            a1 = fmaf(hTrow[33 * j + u0 + 16],        wout_s[j],      a1);
            b0 = fmaf(hTrow[33 * (j + 16) + u0],      wout_s[j + 16], b0);
            b1 = fmaf(hTrow[33 * (j + 16) + u0 + 16], wout_s[j + 16], b1);
        }
        yrow[t0 + u0]      = a0 + b0;         // coalesced per half-warp
        yrow[t0 + u0 + 16] = a1 + b1;
        __syncwarp();                          // hT WAR guard, 1 per 32 steps

        xv0 = xn0;
        xv1 = xn1;
    }

    {
        float hA, hB; unpack2(h2, hA, hB);
        hn[(size_t)row * H + u0] = hA;
        hn[(size_t)row * H + u1] = hB;
    }
}

extern "C" void kernel_launch(void* const* d_in, const int* in_sizes, int n_in,
                              void* d_out, int out_size) {
    const float* x     = (const float*)d_in[0];   // [B,T,1]
    const float* h0    = (const float*)d_in[1];   // [1,B,H]
    const float* W_ih  = (const float*)d_in[2];   // [3H,1]
    const float* W_hh  = (const float*)d_in[3];   // [3H,H]
    const float* b_ih  = (const float*)d_in[4];   // [3H]
    const float* b_hh  = (const float*)d_in[5];   // [3H]
    const float* W_out = (const float*)d_in[6];   // [1,H]
    const float* b_out = (const float*)d_in[7];   // [1]
    float* out = (float*)d_out;

    const int B = in_sizes[1] / H;                // 2048
    const int T = in_sizes[0] / B;                // 1024

    float* y  = out;                              // [B,T]
    float* hn = out + (size_t)B * T;              // [B,H]

    static bool attr_set = false;                 // idempotent; safe pre-capture
    if (!attr_set) {
        cudaFuncSetAttribute(gru_warp_kernel,
                             cudaFuncAttributeMaxDynamicSharedMemorySize,
                             SMEM_BYTES);
        attr_set = true;
    }

    const int npairs = B / 2;                     // 1024
    const int grid = (npairs + WPB - 1) / WPB;    // 147 -> all SMs, single wave
    gru_warp_kernel<<<grid, THREADS, SMEM_BYTES>>>(x, h0, W_ih, W_hh, b_ih, b_hh,
                                                   W_out, b_out, y, hn, B, T);
}

// round 15
// speedup vs baseline: 1.0474x; 1.0474x over previous
#include <cuda_runtime.h>

#define H 32
#define WPB 7            // warps per block; each warp = 2 batch rows
#define THREADS (WPB*32)
#define CHUNK 32         // deferred-output chunk (dynamic smem)
#define RSTRIDE 48       // ring: row B offset (floats) -> 16-bank shift
#define TSTR2R 1072      // hT: row B offset within warp (1072%32==16)
#define HT_WSTR 2144     // hT: per-warp stride (2144%32==0, pattern preserved)

// dynamic smem layout (floats):
//   [0, 1344)        ring  [WPB][2][2*RSTRIDE]
//   [1344, 1377)     wout  [H+1] ([32]=b_out)
//   [1392, 16400)    hT    per warp HT_WSTR, per row TSTR2R, unit stride 33
#define RING_OFF 0
#define WOUT_OFF 1344
#define HT_OFF   1392
#define SMEM_FLOATS 16400
#define SMEM_BYTES (SMEM_FLOATS * 4)

typedef unsigned long long ull;

// zero-instruction ordering fence (same-warp MIO is in-order; R9/R12 verified)
#define CFENCE() asm volatile("" ::: "memory")

// ---------- packed f32x2 helpers (sm_103a dual FP32 pipe) ----------
__device__ __forceinline__ ull ffma2(ull a, ull b, ull c) {
    ull d;
    asm("fma.rn.f32x2 %0, %1, %2, %3;" : "=l"(d) : "l"(a), "l"(b), "l"(c));
    return d;
}
__device__ __forceinline__ ull mulf2(ull a, ull b) {
    ull d;
    asm("mul.rn.f32x2 %0, %1, %2;" : "=l"(d) : "l"(a), "l"(b));
    return d;
}
__device__ __forceinline__ float hsum2(ull a) {
    float lo, hi;
    asm("mov.b64 {%0, %1}, %2;" : "=f"(lo), "=f"(hi) : "l"(a));
    return lo + hi;
}
__device__ __forceinline__ float tanh_ap(float x) {
    float r; asm("tanh.approx.f32 %0, %1;" : "=f"(r) : "f"(x)); return r;
}
__device__ __forceinline__ ull pack2(float lo, float hi) {
    ull d;
    asm("mov.b64 %0, {%1, %2};" : "=l"(d) : "f"(lo), "f"(hi));
    return d;
}

// One warp = 2 batch rows (half-warp per row); lane owns hidden units u0, u0+16
// of its row. Step is GATE-PHASED: r/z dots first (their tanhs start early),
// n-gate dots second so they hide the r/z tanh latency.
// grid=147 x 7 warps covers 1024 row-pairs, single wave, all SMs.
__global__ void __launch_bounds__(THREADS, 1)
gru_warp_kernel(const float* __restrict__ x,     // [B,T]
                const float* __restrict__ h0,    // [B,H]
                const float* __restrict__ W_ih,  // [3H] (I=1)
                const float* __restrict__ W_hh,  // [3H,H]
                const float* __restrict__ b_ih,  // [3H]
                const float* __restrict__ b_hh,  // [3H]
                const float* __restrict__ W_out, // [H]
                const float* __restrict__ b_out, // [1]
                float* __restrict__ y,           // [B,T]
                float* __restrict__ hn,          // [B,H]
                int B, int T)
{
    extern __shared__ __align__(16) float smem[];
    float* ring   = smem + RING_OFF;
    float* wout_s = smem + WOUT_OFF;
    float* hTall  = smem + HT_OFF;

    const int lane = threadIdx.x & 31;
    const int w    = threadIdx.x >> 5;
    const int npairs = B >> 1;
    const int p    = blockIdx.x * WPB + w;

    if (threadIdx.x < H) wout_s[threadIdx.x] = W_out[threadIdx.x];
    if (threadIdx.x == H) wout_s[H] = b_out[0];
    __syncthreads();
    if (p >= npairs) return;

    const int u0  = lane & 15;     // first hidden unit this lane owns
    const int r   = lane >> 4;     // which row of the pair this half-warp runs
    const int row = 2 * p + r;     // global batch row

    // ---- recurrent weights for units u0 and u0+16 (6 gate rows), packed pairs.
    //      r/z rows pre-scaled by 0.5: sigmoid(a) = 0.5 + 0.5*tanh(a/2). ----
    ull Wr0[16], Wz0[16], Wn0[16], Wr1[16], Wz1[16], Wn1[16];
    {
        const ull HALF2 = 0x3F0000003F000000ull;  // (0.5f, 0.5f)
        const int u1 = u0 + 16;
        const ull* wr0 = (const ull*)(W_hh + (size_t)u0 * H);
        const ull* wz0 = (const ull*)(W_hh + (size_t)(H + u0) * H);
        const ull* wn0 = (const ull*)(W_hh + (size_t)(2 * H + u0) * H);
        const ull* wr1 = (const ull*)(W_hh + (size_t)u1 * H);
        const ull* wz1 = (const ull*)(W_hh + (size_t)(H + u1) * H);
        const ull* wn1 = (const ull*)(W_hh + (size_t)(2 * H + u1) * H);
        #pragma unroll
        for (int k = 0; k < 16; k++) {
            Wr0[k] = mulf2(wr0[k], HALF2);
            Wz0[k] = mulf2(wz0[k], HALF2);
            Wn0[k] = wn0[k];
            Wr1[k] = mulf2(wr1[k], HALF2);
            Wz1[k] = mulf2(wz1[k], HALF2);
            Wn1[k] = wn1[k];
        }
    }
    const int u1 = u0 + 16;
    const float wihr0 = 0.5f * W_ih[u0],    wihr1 = 0.5f * W_ih[u1];
    const float wihz0 = 0.5f * W_ih[H + u0], wihz1 = 0.5f * W_ih[H + u1];
    const float wihn0 = W_ih[2 * H + u0],   wihn1 = W_ih[2 * H + u1];
    // ALL gate biases folded into accumulator inits (lo half of packed pair)
    const ull ir0 = pack2(0.5f * (b_ih[u0] + b_hh[u0]), 0.0f);
    const ull ir1 = pack2(0.5f * (b_ih[u1] + b_hh[u1]), 0.0f);
    const ull iz0 = pack2(0.5f * (b_ih[H + u0] + b_hh[H + u0]), 0.0f);
    const ull iz1 = pack2(0.5f * (b_ih[H + u1] + b_hh[H + u1]), 0.0f);
    const ull in0 = pack2(b_hh[2 * H + u0], 0.0f);   // n hidden bias (inside r*)
    const ull in1 = pack2(b_hh[2 * H + u1], 0.0f);
    const float bin0 = b_ih[2 * H + u0], bin1 = b_ih[2 * H + u1];

    float* ringw = ring + w * (2 * 2 * RSTRIDE);     // [2][96]
    float* hTrow = hTall + w * HT_WSTR + r * TSTR2R; // this row's 32x33 history

    float hA = h0[(size_t)row * H + u0];
    float hB = h0[(size_t)row * H + u1];
    ringw[96 + r * RSTRIDE + u0] = hA;     // step 0 reads parity 1
    ringw[96 + r * RSTRIDE + u1] = hB;
    __syncwarp();

    const float* xrow = x + (size_t)row * T;
    float*       yrow = y + (size_t)row * T;

    float xv0 = xrow[u0];                  // first chunk x, steps 0..15
    float xv1 = xrow[16 + u0];             // first chunk x, steps 16..31

    for (int t0 = 0; t0 < T; t0 += CHUNK) {
        #pragma unroll 2
        for (int s = 0; s < CHUNK; s++) {
            const int rd = (s & 1) ^ 1;
            const int wb = (s & 1);

            const float xsrc = (s & 16) ? xv1 : xv0;
            const float xt = __shfl_sync(0xffffffffu, xsrc, s & 15, 16);

            const ulonglong2* hp = (const ulonglong2*)&ringw[rd * 96 + r * RSTRIDE];

            // ---- phase A: r and z gate dots (4 chains, 64 FFMA2) ----
            ull ar0 = ir0, az0 = iz0;
            ull ar1 = ir1, az1 = iz1;
            #pragma unroll
            for (int q = 0; q < 8; q++) {
                const ulonglong2 hv = hp[q];
                ar0 = ffma2(hv.x, Wr0[2 * q],     ar0);
                az0 = ffma2(hv.x, Wz0[2 * q],     az0);
                ar1 = ffma2(hv.x, Wr1[2 * q],     ar1);
                az1 = ffma2(hv.x, Wz1[2 * q],     az1);
                ar0 = ffma2(hv.y, Wr0[2 * q + 1], ar0);
                az0 = ffma2(hv.y, Wz0[2 * q + 1], az0);
                ar1 = ffma2(hv.y, Wr1[2 * q + 1], ar1);
                az1 = ffma2(hv.y, Wz1[2 * q + 1], az1);
            }
            // r/z epilogue: tanhs start while phase B issues below
            const float rg0 = fmaf(0.5f, tanh_ap(fmaf(xt, wihr0, hsum2(ar0))), 0.5f);
            const float zg0 = fmaf(0.5f, tanh_ap(fmaf(xt, wihz0, hsum2(az0))), 0.5f);
            const float rg1 = fmaf(0.5f, tanh_ap(fmaf(xt, wihr1, hsum2(ar1))), 0.5f);
            const float zg1 = fmaf(0.5f, tanh_ap(fmaf(xt, wihz1, hsum2(az1))), 0.5f);

            // ---- phase B: n gate dots (2 chains, 32 FFMA2) — these issue
            //      under the r/z tanh latency ----
            ull an0 = in0, an1 = in1;
            #pragma unroll
            for (int q = 0; q < 8; q++) {
                const ulonglong2 hv = hp[q];
                an0 = ffma2(hv.x, Wn0[2 * q],     an0);
                an1 = ffma2(hv.x, Wn1[2 * q],     an1);
                an0 = ffma2(hv.y, Wn0[2 * q + 1], an0);
                an1 = ffma2(hv.y, Wn1[2 * q + 1], an1);
            }
            // n epilogue + h update
            const float ng0 = tanh_ap(fmaf(rg0, hsum2(an0), fmaf(xt, wihn0, bin0)));
            const float ng1 = tanh_ap(fmaf(rg1, hsum2(an1), fmaf(xt, wihn1, bin1)));
            hA = fmaf(zg0, hA - ng0, ng0);
            hB = fmaf(zg1, hB - ng1, ng1);

            ringw[wb * 96 + r * RSTRIDE + u0] = hA;
            ringw[wb * 96 + r * RSTRIDE + u1] = hB;
            hTrow[33 * u0 + s] = hA;          // conflict-free (derived bank map)
            hTrow[33 * u1 + s] = hB;
            CFENCE();         // same-warp in-order MIO: no WARPSYNC needed
        }

        // Prefetch next chunk's x while the y-phase runs.
        float xn0 = 0.0f, xn1 = 0.0f;
        if (t0 + CHUNK < T) {
            xn0 = xrow[t0 + CHUNK + u0];
            xn1 = xrow[t0 + CHUNK + 16 + u0];
        }

        // Deferred y: each lane produces 2 outputs (row r, steps u0 and u0+16),
        // 4 independent 16-deep FMA chains to cut exposed latency.
        float a0 = wout_s[H], a1 = wout_s[H];   // b_out folded into init
        float b0 = 0.0f,      b1 = 0.0f;
        #pragma unroll
        for (int j = 0; j < 16; j++) {
            a0 = fmaf(hTrow[33 * j + u0],             wout_s[j],      a0);
            a1 = fmaf(hTrow[33 * j + u0 + 16],        wout_s[j],      a1);
            b0 = fmaf(hTrow[33 * (j + 16) + u0],      wout_s[j + 16], b0);
            b1 = fmaf(hTrow[33 * (j + 16) + u0 + 16], wout_s[j + 16], b1);
        }
        yrow[t0 + u0]      = a0 + b0;         // coalesced per half-warp
        yrow[t0 + u0 + 16] = a1 + b1;
        __syncwarp();                          // hT WAR guard, 1 per 32 steps

        xv0 = xn0;
        xv1 = xn1;
    }

    hn[(size_t)row * H + u0] = hA;
    hn[(size_t)row * H + u1] = hB;
}

extern "C" void kernel_launch(void* const* d_in, const int* in_sizes, int n_in,
                              void* d_out, int out_size) {
    const float* x     = (const float*)d_in[0];   // [B,T,1]
    const float* h0    = (const float*)d_in[1];   // [1,B,H]
    const float* W_ih  = (const float*)d_in[2];   // [3H,1]
    const float* W_hh  = (const float*)d_in[3];   // [3H,H]
    const float* b_ih  = (const float*)d_in[4];   // [3H]
    const float* b_hh  = (const float*)d_in[5];   // [3H]
    const float* W_out = (const float*)d_in[6];   // [1,H]
    const float* b_out = (const float*)d_in[7];   // [1]
    float* out = (float*)d_out;

    const int B = in_sizes[1] / H;                // 2048
    const int T = in_sizes[0] / B;                // 1024

    float* y  = out;                              // [B,T]
    float* hn = out + (size_t)B * T;              // [B,H]

    static bool attr_set = false;                 // idempotent; safe pre-capture
    if (!attr_set) {
        cudaFuncSetAttribute(gru_warp_kernel,
                             cudaFuncAttributeMaxDynamicSharedMemorySize,
                             SMEM_BYTES);
        attr_set = true;
    }

    const int npairs = B / 2;                     // 1024
    const int grid = (npairs + WPB - 1) / WPB;    // 147 -> all SMs, single wave
    gru_warp_kernel<<<grid, THREADS, SMEM_BYTES>>>(x, h0, W_ih, W_hh, b_ih, b_hh,
                                                   W_out, b_out, y, hn, B, T);
}

// round 16
// speedup vs baseline: 1.0623x; 1.0142x over previous
#include <cuda_runtime.h>

#define H 32
#define WPB 7            // warps per block; each warp = 2 batch rows
#define THREADS (WPB*32)
#define CHUNK 32         // deferred-output chunk

typedef unsigned long long ull;

// dynamic smem layout:
//   ull units:
//     ring2: [0, 672)    per warp 96 ull: [parity(2)][row(2)][24 ull (16 used)]
//     hT2  : [672, 8078) per warp 1058 ull: [row(2)][529]; pair-row stride 33
//   float units (after ull region):
//     wout : [16156, 16189)   ([32]=b_out)
#define RING_WSTR 96
#define RING_PSTR 48
#define RING_RSTR 24
#define HT2_OFF  672
#define HT2_RSTR 529
#define HT2_WSTR 1058
#define WOUT_F   16156
#define SMEM_FLOATS 16192
#define SMEM_BYTES (SMEM_FLOATS * 4)

// zero-instruction ordering fence (same-warp MIO is in-order; R9/R12 verified)
#define CFENCE() asm volatile("" ::: "memory")

// ---------- packed f32x2 helpers (sm_103a dual FP32 pipe) ----------
__device__ __forceinline__ ull ffma2(ull a, ull b, ull c) {
    ull d;
    asm("fma.rn.f32x2 %0, %1, %2, %3;" : "=l"(d) : "l"(a), "l"(b), "l"(c));
    return d;
}
__device__ __forceinline__ float hsum2(ull a) {
    float lo, hi;
    asm("mov.b64 {%0, %1}, %2;" : "=f"(lo), "=f"(hi) : "l"(a));
    return lo + hi;
}
__device__ __forceinline__ float tanh_ap(float x) {
    float r; asm("tanh.approx.f32 %0, %1;" : "=f"(r) : "f"(x)); return r;
}
__device__ __forceinline__ ull pack2(float lo, float hi) {
    ull d;
    asm("mov.b64 %0, {%1, %2};" : "=l"(d) : "f"(lo), "f"(hi));
    return d;
}
__device__ __forceinline__ void unpack2(ull a, float& lo, float& hi) {
    asm("mov.b64 {%0, %1}, %2;" : "=f"(lo), "=f"(hi) : "l"(a));
}

// One warp = 2 batch rows (half-warp per row); lane owns units (u0, u0+16).
// Unit-INTERLEAVED smem layout: ring and hT hold (h_u, h_{u+16}) as single
// 64-bit entries -> ring store 1xSTS.64, hT store 1xSTS.64, y-phase LDS.64:
// ~20% fewer MIO issues per step. Weights re-paired (W[u][j], W[u][j+16]) so
// the LDS.128 dot loop is unchanged; acc lo/hi = k<16 / k>=16 partial sums.
// grid=147 x 7 warps covers 1024 row-pairs, single wave, all SMs.
__global__ void __launch_bounds__(THREADS, 1)
gru_warp_kernel(const float* __restrict__ x,     // [B,T]
                const float* __restrict__ h0,    // [B,H]
                const float* __restrict__ W_ih,  // [3H] (I=1)
                const float* __restrict__ W_hh,  // [3H,H]
                const float* __restrict__ b_ih,  // [3H]
                const float* __restrict__ b_hh,  // [3H]
                const float* __restrict__ W_out, // [H]
                const float* __restrict__ b_out, // [1]
                float* __restrict__ y,           // [B,T]
                float* __restrict__ hn,          // [B,H]
                int B, int T)
{
    extern __shared__ __align__(16) ull smem_u[];
    ull*   ring2  = smem_u;
    ull*   hT2    = smem_u + HT2_OFF;
    float* wout_s = (float*)smem_u + WOUT_F;

    const int lane = threadIdx.x & 31;
    const int w    = threadIdx.x >> 5;
    const int npairs = B >> 1;
    const int p    = blockIdx.x * WPB + w;

    if (threadIdx.x < H) wout_s[threadIdx.x] = W_out[threadIdx.x];
    if (threadIdx.x == H) wout_s[H] = b_out[0];
    __syncthreads();
    if (p >= npairs) return;

    const int u0  = lane & 15;     // first hidden unit this lane owns
    const int r   = lane >> 4;     // which row of the pair this half-warp runs
    const int row = 2 * p + r;     // global batch row
    const int u1  = u0 + 16;

    // ---- weights for units u0/u1, paired for the INTERLEAVED h layout:
    //      Wg[j] = (Wg[u][j], Wg[u][j+16]); r/z pre-scaled by 0.5. ----
    ull Wr0[16], Wz0[16], Wn0[16], Wr1[16], Wz1[16], Wn1[16];
    {
        const float* wr0 = W_hh + (size_t)u0 * H;
        const float* wz0 = W_hh + (size_t)(H + u0) * H;
        const float* wn0 = W_hh + (size_t)(2 * H + u0) * H;
        const float* wr1 = W_hh + (size_t)u1 * H;
        const float* wz1 = W_hh + (size_t)(H + u1) * H;
        const float* wn1 = W_hh + (size_t)(2 * H + u1) * H;
        #pragma unroll
        for (int j = 0; j < 16; j++) {
            Wr0[j] = pack2(0.5f * wr0[j], 0.5f * wr0[j + 16]);
            Wz0[j] = pack2(0.5f * wz0[j], 0.5f * wz0[j + 16]);
            Wn0[j] = pack2(wn0[j],        wn0[j + 16]);
            Wr1[j] = pack2(0.5f * wr1[j], 0.5f * wr1[j + 16]);
            Wz1[j] = pack2(0.5f * wz1[j], 0.5f * wz1[j + 16]);
            Wn1[j] = pack2(wn1[j],        wn1[j + 16]);
        }
    }
    const float wihr0 = 0.5f * W_ih[u0],    wihr1 = 0.5f * W_ih[u1];
    const float wihz0 = 0.5f * W_ih[H + u0], wihz1 = 0.5f * W_ih[H + u1];
    const float wihn0 = W_ih[2 * H + u0],   wihn1 = W_ih[2 * H + u1];
    // gate biases folded into accumulator inits (lo half of packed pair)
    const ull ir0 = pack2(0.5f * (b_ih[u0] + b_hh[u0]), 0.0f);
    const ull ir1 = pack2(0.5f * (b_ih[u1] + b_hh[u1]), 0.0f);
    const ull iz0 = pack2(0.5f * (b_ih[H + u0] + b_hh[H + u0]), 0.0f);
    const ull iz1 = pack2(0.5f * (b_ih[H + u1] + b_hh[H + u1]), 0.0f);
    const ull in0 = pack2(b_hh[2 * H + u0], 0.0f);   // n hidden bias (inside r*)
    const ull in1 = pack2(b_hh[2 * H + u1], 0.0f);
    const float bin0 = b_ih[2 * H + u0], bin1 = b_ih[2 * H + u1];

    ull* ring2w = ring2 + w * RING_WSTR + r * RING_RSTR;  // + parity*RING_PSTR
    ull* hT2row = hT2 + w * HT2_WSTR + r * HT2_RSTR;      // pair u0 at +u0*33

    float hA = h0[(size_t)row * H + u0];
    float hB = h0[(size_t)row * H + u1];
    ring2w[RING_PSTR + u0] = pack2(hA, hB);   // step 0 reads parity 1
    __syncwarp();

    const float* xrow = x + (size_t)row * T;
    float*       yrow = y + (size_t)row * T;

    float xv0 = xrow[u0];                  // first chunk x, steps 0..15
    float xv1 = xrow[16 + u0];             // first chunk x, steps 16..31

    for (int t0 = 0; t0 < T; t0 += CHUNK) {
        #pragma unroll 2
        for (int s = 0; s < CHUNK; s++) {
            const int rd = (s & 1) ^ 1;
            const int wb = (s & 1);

            const float xsrc = (s & 16) ? xv1 : xv0;
            const float xt = __shfl_sync(0xffffffffu, xsrc, s & 15, 16);

            // hp[q]: (h_{2q},h_{2q+16}) , (h_{2q+1},h_{2q+17})
            const ulonglong2* hp = (const ulonglong2*)(ring2w + rd * RING_PSTR);
            ull ar0 = ir0, az0 = iz0, an0 = in0;
            ull ar1 = ir1, az1 = iz1, an1 = in1;
            #pragma unroll
            for (int q = 0; q < 8; q++) {
                const ulonglong2 hv = hp[q];
                ar0 = ffma2(hv.x, Wr0[2 * q],     ar0);
                az0 = ffma2(hv.x, Wz0[2 * q],     az0);
                an0 = ffma2(hv.x, Wn0[2 * q],     an0);
                ar1 = ffma2(hv.x, Wr1[2 * q],     ar1);
                az1 = ffma2(hv.x, Wz1[2 * q],     az1);
                an1 = ffma2(hv.x, Wn1[2 * q],     an1);
                ar0 = ffma2(hv.y, Wr0[2 * q + 1], ar0);
                az0 = ffma2(hv.y, Wz0[2 * q + 1], az0);
                an0 = ffma2(hv.y, Wn0[2 * q + 1], an0);
                ar1 = ffma2(hv.y, Wr1[2 * q + 1], ar1);
                az1 = ffma2(hv.y, Wz1[2 * q + 1], az1);
                an1 = ffma2(hv.y, Wn1[2 * q + 1], an1);
            }
            // unit u0
            {
                const float rg = fmaf(0.5f, tanh_ap(fmaf(xt, wihr0, hsum2(ar0))), 0.5f);
                const float zg = fmaf(0.5f, tanh_ap(fmaf(xt, wihz0, hsum2(az0))), 0.5f);
                const float ng = tanh_ap(fmaf(rg, hsum2(an0), fmaf(xt, wihn0, bin0)));
                hA = fmaf(zg, hA - ng, ng);
            }
            // unit u0+16
            {
                const float rg = fmaf(0.5f, tanh_ap(fmaf(xt, wihr1, hsum2(ar1))), 0.5f);
                const float zg = fmaf(0.5f, tanh_ap(fmaf(xt, wihz1, hsum2(az1))), 0.5f);
                const float ng = tanh_ap(fmaf(rg, hsum2(an1), fmaf(xt, wihn1, bin1)));
                hB = fmaf(zg, hB - ng, ng);
            }

            const ull h2 = pack2(hA, hB);
            ring2w[wb * RING_PSTR + u0] = h2;   // 1x STS.64 (was 2x STS.32)
            hT2row[u0 * 33 + s]         = h2;   // 1x STS.64 (was 2x STS.32)
            CFENCE();         // same-warp in-order MIO: no WARPSYNC needed
        }

        // Prefetch next chunk's x while the y-phase runs.
        float xn0 = 0.0f, xn1 = 0.0f;
        if (t0 + CHUNK < T) {
            xn0 = xrow[t0 + CHUNK + u0];
            xn1 = xrow[t0 + CHUNK + 16 + u0];
        }

        // Deferred y: lane produces outputs for steps u0 and u0+16 of its row.
        // Each output: 16 LDS.64 (pair (h_j, h_{j+16})) + 32 fmaf, two
        // independent chains per output.
        float a0 = wout_s[H], a1 = wout_s[H];   // b_out folded into init
        float b0 = 0.0f,      b1 = 0.0f;
        #pragma unroll
        for (int j = 0; j < 16; j++) {
            float hj0, hj1;
            unpack2(hT2row[j * 33 + u0], hj0, hj1);
            a0 = fmaf(hj0, wout_s[j],      a0);
            b0 = fmaf(hj1, wout_s[j + 16], b0);
            float hk0, hk1;
            unpack2(hT2row[j * 33 + u0 + 16], hk0, hk1);
            a1 = fmaf(hk0, wout_s[j],      a1);
            b1 = fmaf(hk1, wout_s[j + 16], b1);
        }
        yrow[t0 + u0]      = a0 + b0;         // coalesced per half-warp
        yrow[t0 + u0 + 16] = a1 + b1;
        __syncwarp();                          // hT WAR guard, 1 per 32 steps

        xv0 = xn0;
        xv1 = xn1;
    }

    hn[(size_t)row * H + u0] = hA;
    hn[(size_t)row * H + u1] = hB;
}

extern "C" void kernel_launch(void* const* d_in, const int* in_sizes, int n_in,
                              void* d_out, int out_size) {
    const float* x     = (const float*)d_in[0];   // [B,T,1]
    const float* h0    = (const float*)d_in[1];   // [1,B,H]
    const float* W_ih  = (const float*)d_in[2];   // [3H,1]
    const float* W_hh  = (const float*)d_in[3];   // [3H,H]
    const float* b_ih  = (const float*)d_in[4];   // [3H]
    const float* b_hh  = (const float*)d_in[5];   // [3H]
    const float* W_out = (const float*)d_in[6];   // [1,H]
    const float* b_out = (const float*)d_in[7];   // [1]
    float* out = (float*)d_out;

    const int B = in_sizes[1] / H;                // 2048
    const int T = in_sizes[0] / B;                // 1024

    float* y  = out;                              // [B,T]
    float* hn = out + (size_t)B * T;              // [B,H]

    static bool attr_set = false;                 // idempotent; safe pre-capture
    if (!attr_set) {
        cudaFuncSetAttribute(gru_warp_kernel,
                             cudaFuncAttributeMaxDynamicSharedMemorySize,
                             SMEM_BYTES);
        attr_set = true;
    }

    const int npairs = B / 2;                     // 1024
    const int grid = (npairs + WPB - 1) / WPB;    // 147 -> all SMs, single wave
    gru_warp_kernel<<<grid, THREADS, SMEM_BYTES>>>(x, h0, W_ih, W_hh, b_ih, b_hh,
                                                   W_out, b_out, y, hn, B, T);
}

// round 17
// speedup vs baseline: 1.0834x; 1.0199x over previous
#include <cuda_runtime.h>

#define H 32
#define WPB 7            // warps per block; each warp = 2 batch rows
#define THREADS (WPB*32)
#define CHUNK 32         // deferred-output chunk

typedef unsigned long long ull;

// dynamic smem layout (ull units):
//   hT2: per warp 1152 ull = [row r (2)][step s (32) x 18 ull]
//        row s holds the 16 interleaved pairs (h_u, h_{u+16}) of step s;
//        stride 18 ull = 144B (16B-aligned for LDS.128, 4-bank shift per row).
//        Serves BOTH the next-step broadcast read (row s-1, contiguous,
//        8x LDS.128) and the deferred-y column reads. No separate ring.
//   wout (float units, after ull region): [32]=b_out
#define HT2_RSTR 576              // per-row-of-pair stride (32*18)
#define HT2_WSTR 1152             // per-warp stride
#define WOUT_F   16128            // float offset of wout (7*1152 ull * 2)
#define SMEM_FLOATS 16164
#define SMEM_BYTES (SMEM_FLOATS * 4)

// zero-instruction ordering fence (same-warp MIO is in-order; R9/R12 verified)
#define CFENCE() asm volatile("" ::: "memory")

// ---------- packed f32x2 helpers (sm_103a dual FP32 pipe) ----------
__device__ __forceinline__ ull ffma2(ull a, ull b, ull c) {
    ull d;
    asm("fma.rn.f32x2 %0, %1, %2, %3;" : "=l"(d) : "l"(a), "l"(b), "l"(c));
    return d;
}
__device__ __forceinline__ float hsum2(ull a) {
    float lo, hi;
    asm("mov.b64 {%0, %1}, %2;" : "=f"(lo), "=f"(hi) : "l"(a));
    return lo + hi;
}
__device__ __forceinline__ float tanh_ap(float x) {
    float r; asm("tanh.approx.f32 %0, %1;" : "=f"(r) : "f"(x)); return r;
}
__device__ __forceinline__ ull pack2(float lo, float hi) {
    ull d;
    asm("mov.b64 %0, {%1, %2};" : "=l"(d) : "f"(lo), "f"(hi));
    return d;
}
__device__ __forceinline__ void unpack2(ull a, float& lo, float& hi) {
    asm("mov.b64 {%0, %1}, %2;" : "=f"(lo), "=f"(hi) : "l"(a));
}

// One warp = 2 batch rows (half-warp per row); lane owns units (u0, u0+16),
// stored as ONE interleaved 64-bit pair. Step s reads step s-1's row
// (broadcast LDS.128) and writes its own row with a single STS.64 —
// 10 MIO issues per warp-step. Weights paired (W[u][j], W[u][j+16]).
// grid=147 x 7 warps covers 1024 row-pairs, single wave, all SMs.
__global__ void __launch_bounds__(THREADS, 1)
gru_warp_kernel(const float* __restrict__ x,     // [B,T]
                const float* __restrict__ h0,    // [B,H]
                const float* __restrict__ W_ih,  // [3H] (I=1)
                const float* __restrict__ W_hh,  // [3H,H]
                const float* __restrict__ b_ih,  // [3H]
                const float* __restrict__ b_hh,  // [3H]
                const float* __restrict__ W_out, // [H]
                const float* __restrict__ b_out, // [1]
                float* __restrict__ y,           // [B,T]
                float* __restrict__ hn,          // [B,H]
                int B, int T)
{
    extern __shared__ __align__(16) ull smem_u[];
    ull*   hT2    = smem_u;
    float* wout_s = (float*)smem_u + WOUT_F;

    const int lane = threadIdx.x & 31;
    const int w    = threadIdx.x >> 5;
    const int npairs = B >> 1;
    const int p    = blockIdx.x * WPB + w;

    if (threadIdx.x < H) wout_s[threadIdx.x] = W_out[threadIdx.x];
    if (threadIdx.x == H) wout_s[H] = b_out[0];
    __syncthreads();
    if (p >= npairs) return;

    const int u0  = lane & 15;     // first hidden unit this lane owns
    const int r   = lane >> 4;     // which row of the pair this half-warp runs
    const int row = 2 * p + r;     // global batch row
    const int u1  = u0 + 16;

    // ---- weights for units u0/u1, paired for the INTERLEAVED h layout:
    //      Wg[j] = (Wg[u][j], Wg[u][j+16]); r/z pre-scaled by 0.5. ----
    ull Wr0[16], Wz0[16], Wn0[16], Wr1[16], Wz1[16], Wn1[16];
    {
        const float* wr0 = W_hh + (size_t)u0 * H;
        const float* wz0 = W_hh + (size_t)(H + u0) * H;
        const float* wn0 = W_hh + (size_t)(2 * H + u0) * H;
        const float* wr1 = W_hh + (size_t)u1 * H;
        const float* wz1 = W_hh + (size_t)(H + u1) * H;
        const float* wn1 = W_hh + (size_t)(2 * H + u1) * H;
        #pragma unroll
        for (int j = 0; j < 16; j++) {
            Wr0[j] = pack2(0.5f * wr0[j], 0.5f * wr0[j + 16]);
            Wz0[j] = pack2(0.5f * wz0[j], 0.5f * wz0[j + 16]);
            Wn0[j] = pack2(wn0[j],        wn0[j + 16]);
            Wr1[j] = pack2(0.5f * wr1[j], 0.5f * wr1[j + 16]);
            Wz1[j] = pack2(0.5f * wz1[j], 0.5f * wz1[j + 16]);
            Wn1[j] = pack2(wn1[j],        wn1[j + 16]);
        }
    }
    const float wihr0 = 0.5f * W_ih[u0],    wihr1 = 0.5f * W_ih[u1];
    const float wihz0 = 0.5f * W_ih[H + u0], wihz1 = 0.5f * W_ih[H + u1];
    const float wihn0 = W_ih[2 * H + u0],   wihn1 = W_ih[2 * H + u1];
    // gate biases folded into accumulator inits (lo half of packed pair)
    const ull ir0 = pack2(0.5f * (b_ih[u0] + b_hh[u0]), 0.0f);
    const ull ir1 = pack2(0.5f * (b_ih[u1] + b_hh[u1]), 0.0f);
    const ull iz0 = pack2(0.5f * (b_ih[H + u0] + b_hh[H + u0]), 0.0f);
    const ull iz1 = pack2(0.5f * (b_ih[H + u1] + b_hh[H + u1]), 0.0f);
    const ull in0 = pack2(b_hh[2 * H + u0], 0.0f);   // n hidden bias (inside r*)
    const ull in1 = pack2(b_hh[2 * H + u1], 0.0f);
    const float bin0 = b_ih[2 * H + u0], bin1 = b_ih[2 * H + u1];

    ull* hT2row = hT2 + w * HT2_WSTR + r * HT2_RSTR;  // this row's 32x18 history

    float hA = h0[(size_t)row * H + u0];
    float hB = h0[(size_t)row * H + u1];
    hT2row[31 * 18 + u0] = pack2(hA, hB);   // step 0 reads row 31
    __syncwarp();

    const float* xrow = x + (size_t)row * T;
    float*       yrow = y + (size_t)row * T;

    float xv0 = xrow[u0];                  // first chunk x, steps 0..15
    float xv1 = xrow[16 + u0];             // first chunk x, steps 16..31

    for (int t0 = 0; t0 < T; t0 += CHUNK) {
        #pragma unroll 2
        for (int s = 0; s < CHUNK; s++) {
            const int prev = (s + 31) & 31;           // row written last step

            const float xsrc = (s & 16) ? xv1 : xv0;
            const float xt = __shfl_sync(0xffffffffu, xsrc, s & 15, 16);

            // hp[q]: (h_{2q},h_{2q+16}) , (h_{2q+1},h_{2q+17}) — broadcast
            const ulonglong2* hp = (const ulonglong2*)(hT2row + prev * 18);
            ull ar0 = ir0, az0 = iz0, an0 = in0;
            ull ar1 = ir1, az1 = iz1, an1 = in1;
            #pragma unroll
            for (int q = 0; q < 8; q++) {
                const ulonglong2 hv = hp[q];
                ar0 = ffma2(hv.x, Wr0[2 * q],     ar0);
                az0 = ffma2(hv.x, Wz0[2 * q],     az0);
                an0 = ffma2(hv.x, Wn0[2 * q],     an0);
                ar1 = ffma2(hv.x, Wr1[2 * q],     ar1);
                az1 = ffma2(hv.x, Wz1[2 * q],     az1);
                an1 = ffma2(hv.x, Wn1[2 * q],     an1);
                ar0 = ffma2(hv.y, Wr0[2 * q + 1], ar0);
                az0 = ffma2(hv.y, Wz0[2 * q + 1], az0);
                an0 = ffma2(hv.y, Wn0[2 * q + 1], an0);
                ar1 = ffma2(hv.y, Wr1[2 * q + 1], ar1);
                az1 = ffma2(hv.y, Wz1[2 * q + 1], az1);
                an1 = ffma2(hv.y, Wn1[2 * q + 1], an1);
            }
            // unit u0
            {
                const float rg = fmaf(0.5f, tanh_ap(fmaf(xt, wihr0, hsum2(ar0))), 0.5f);
                const float zg = fmaf(0.5f, tanh_ap(fmaf(xt, wihz0, hsum2(az0))), 0.5f);
                const float ng = tanh_ap(fmaf(rg, hsum2(an0), fmaf(xt, wihn0, bin0)));
                hA = fmaf(zg, hA - ng, ng);
            }
            // unit u0+16
            {
                const float rg = fmaf(0.5f, tanh_ap(fmaf(xt, wihr1, hsum2(ar1))), 0.5f);
                const float zg = fmaf(0.5f, tanh_ap(fmaf(xt, wihz1, hsum2(az1))), 0.5f);
                const float ng = tanh_ap(fmaf(rg, hsum2(an1), fmaf(xt, wihn1, bin1)));
                hB = fmaf(zg, hB - ng, ng);
            }

            hT2row[s * 18 + u0] = pack2(hA, hB);   // single STS.64 per step
            CFENCE();         // same-warp in-order MIO: no WARPSYNC needed
        }

        // Prefetch next chunk's x while the y-phase runs.
        float xn0 = 0.0f, xn1 = 0.0f;
        if (t0 + CHUNK < T) {
            xn0 = xrow[t0 + CHUNK + u0];
            xn1 = xrow[t0 + CHUNK + 16 + u0];
        }

        // Deferred y: lane produces outputs for steps u0 and u0+16 of its row.
        // Row t holds step t's pairs; 16 LDS.64 per output, 2 chains each.
        float a0 = wout_s[H], a1 = wout_s[H];   // b_out folded into init
        float b0 = 0.0f,      b1 = 0.0f;
        #pragma unroll
        for (int j = 0; j < 16; j++) {
            float hj0, hj1;
            unpack2(hT2row[u0 * 18 + j], hj0, hj1);
            a0 = fmaf(hj0, wout_s[j],      a0);
            b0 = fmaf(hj1, wout_s[j + 16], b0);
            float hk0, hk1;
            unpack2(hT2row[(u0 + 16) * 18 + j], hk0, hk1);
            a1 = fmaf(hk0, wout_s[j],      a1);
            b1 = fmaf(hk1, wout_s[j + 16], b1);
        }
        yrow[t0 + u0]      = a0 + b0;         // coalesced per half-warp
        yrow[t0 + u0 + 16] = a1 + b1;
        __syncwarp();   // hT WAR guard: y reads done before next chunk writes

        xv0 = xn0;
        xv1 = xn1;
    }

    hn[(size_t)row * H + u0] = hA;
    hn[(size_t)row * H + u1] = hB;
}

extern "C" void kernel_launch(void* const* d_in, const int* in_sizes, int n_in,
                              void* d_out, int out_size) {
    const float* x     = (const float*)d_in[0];   // [B,T,1]
    const float* h0    = (const float*)d_in[1];   // [1,B,H]
    const float* W_ih  = (const float*)d_in[2];   // [3H,1]
    const float* W_hh  = (const float*)d_in[3];   // [3H,H]
    const float* b_ih  = (const float*)d_in[4];   // [3H]
    const float* b_hh  = (const float*)d_in[5];   // [3H]
    const float* W_out = (const float*)d_in[6];   // [1,H]
    const float* b_out = (const float*)d_in[7];   // [1]
    float* out = (float*)d_out;

    const int B = in_sizes[1] / H;                // 2048
    const int T = in_sizes[0] / B;                // 1024

    float* y  = out;                              // [B,T]
    float* hn = out + (size_t)B * T;              // [B,H]

    static bool attr_set = false;                 // idempotent; safe pre-capture
    if (!attr_set) {
        cudaFuncSetAttribute(gru_warp_kernel,
                             cudaFuncAttributeMaxDynamicSharedMemorySize,
                             SMEM_BYTES);
        attr_set = true;
    }

    const int npairs = B / 2;                     // 1024
    const int grid = (npairs + WPB - 1) / WPB;    // 147 -> all SMs, single wave
    gru_warp_kernel<<<grid, THREADS, SMEM_BYTES>>>(x, h0, W_ih, W_hh, b_ih, b_hh,
                                                   W_out, b_out, y, hn, B, T);
}